// round 14
// baseline (speedup 1.0000x reference)
#include <cuda_runtime.h>

// GainesEdgeDetect first bit-cycle — TERMINAL KERNEL (held from R12).
//
// Exact constant propagation of the reference semantics (R3):
//  * sel=0 (first Sobol draw) -> final MUX takes the Gx path; Gy dead.
//  * Gx = inp_Pr_i_j = x, x in {0,1} (stochastic bit-plane inputs).
//  * Fresh FSUAbs counter cnt = HALF = 8:
//      x=1: clip(8+1)=9 >= 8 -> out = x   = 1
//      x=0: clip(8-1)=7 <  8 -> out = 1-x = 1
//    First abs-bit from a fresh counter is identically 1.
//  => output = constant 1.0f plane: 67.1 MB write-only fill, rel_err 0.0.
//
// Roofline closure (R3-R12): chip-level L2 write-path cap ~6 TB/s
// (L2 pinned 50-52% of peak) — invariant across STG.128 scalar/batched,
// STG.256 (st.global.v8.f32), and TMA cp.async.bulk store agents, and
// across block shapes 256/512/1024 x 1-8 stores/thread. DRAM idle (output
// fits in 126 MB L2). Kernel floor ~11us; harness tail is noise
// (12.48-13.06us on identical binaries). This config holds the best
// recorded result: 12.48us.

#define THREADS 512
#define F4_PER_THREAD 2

__global__ void __launch_bounds__(THREADS)
gaines_edge_fill_kernel(float4* __restrict__ o4) {
    unsigned base = blockIdx.x * (THREADS * F4_PER_THREAD) + threadIdx.x;
    const float4 v = make_float4(1.0f, 1.0f, 1.0f, 1.0f);
#pragma unroll
    for (int j = 0; j < F4_PER_THREAD; j++) {
        o4[base + j * THREADS] = v;
    }
}

extern "C" void kernel_launch(void* const* d_in, const int* in_sizes, int n_in,
                              void* d_out, int out_size) {
    float* out = (float*)d_out;

    int n4 = out_size / 4;                        // 4,194,304 float4s
    int blocks = n4 / (THREADS * F4_PER_THREAD);  // 4096 (exact)

    gaines_edge_fill_kernel<<<blocks, THREADS>>>((float4*)out);
}